// round 14
// baseline (speedup 1.0000x reference)
#include <cuda_runtime.h>
#include <cuda_bf16.h>
#include <cuda_fp16.h>
#include <math.h>

#define NN 50000
#define EE 800000
#define DD 128
#define BN_EPS 1e-5f

typedef unsigned long long u64;
typedef unsigned int u32;
typedef unsigned short u16;

// ---------------- scratch (no allocs allowed) ----------------
__device__ __half g_bufH[NN * DD];    // activations (gather out / gemm in)
__device__ __half g_bufTh[NN * DD];   // transformed messages (gemm out / gather in)
__device__ float  g_dis[NN];
__device__ float  g_stats3[3 * 256];
__device__ int    g_cnt[NN];
__device__ int    g_rowptr[NN];
__device__ int    g_cursor[NN];
__device__ int2   g_epack[EE];        // (src, bitcast(w))
__device__ u16    g_whi[5 * 16384];
__device__ u16    g_wlo[5 * 16384];

// ---------------- mma helpers ----------------
__device__ __forceinline__ u32 su32(const void* p) {
    return (u32)__cvta_generic_to_shared(p);
}
__device__ __forceinline__ void ldsm_x4(u32& r0, u32& r1, u32& r2, u32& r3, u32 addr) {
    asm volatile("ldmatrix.sync.aligned.m8n8.x4.shared.b16 {%0,%1,%2,%3}, [%4];"
                 : "=r"(r0), "=r"(r1), "=r"(r2), "=r"(r3) : "r"(addr));
}
__device__ __forceinline__ void ldsm_x2(u32& r0, u32& r1, u32 addr) {
    asm volatile("ldmatrix.sync.aligned.m8n8.x2.shared.b16 {%0,%1}, [%2];"
                 : "=r"(r0), "=r"(r1) : "r"(addr));
}
__device__ __forceinline__ void mma16816(float* c, const u32* a, const u32* b) {
    asm volatile(
        "mma.sync.aligned.m16n8k16.row.col.f32.bf16.bf16.f32 "
        "{%0,%1,%2,%3}, {%4,%5,%6,%7}, {%8,%9}, {%0,%1,%2,%3};"
        : "+f"(c[0]), "+f"(c[1]), "+f"(c[2]), "+f"(c[3])
        : "r"(a[0]), "r"(a[1]), "r"(a[2]), "r"(a[3]), "r"(b[0]), "r"(b[1]));
}

// ---------------- weight prep (+ zero cnt & stats) ----------------
__global__ void k_prep_w(const float* __restrict__ conv_w, const float* __restrict__ mlp_w) {
    int idx = blockIdx.x * blockDim.x + threadIdx.x;
    if (idx < NN) g_cnt[idx] = 0;
    if (idx < 3 * 256) g_stats3[idx] = 0.f;
    if (idx >= 5 * 16384) return;
    int w = idx >> 14;
    int r = idx & 16383;
    int fout = r >> 7;
    int k = r & 127;
    float v = (w < 3) ? conv_w[w * 16384 + k * 128 + fout]
                      : mlp_w[(w - 3) * 16384 + k * 128 + fout];
    __nv_bfloat16 hi = __float2bfloat16_rn(v);
    __nv_bfloat16 lo = __float2bfloat16_rn(v - __bfloat162float(hi));
    g_whi[idx] = __bfloat16_as_ushort(hi);   // [w][fout][k]
    g_wlo[idx] = __bfloat16_as_ushort(lo);
}

// ---------------- CSR build ----------------
__global__ void k_hist(const int* __restrict__ ei) {
    int e = blockIdx.x * blockDim.x + threadIdx.x;
    if (e < EE) atomicAdd(&g_cnt[ei[EE + e]], 1);
}

// single-block full scan: rowptr/cursor (exclusive) + dis, 1024 threads x 49 elems
#define SCHUNK 49
__global__ void __launch_bounds__(1024) k_scan1() {
    __shared__ int warpsum[32];
    int t = threadIdx.x;
    int lane = t & 31, wid = t >> 5;
    int base = t * SCHUNK;
    int s = 0;
#pragma unroll 7
    for (int j = 0; j < SCHUNK; j++) {
        int i = base + j;
        if (i < NN) s += g_cnt[i];
    }
    int v = s;
#pragma unroll
    for (int o = 1; o < 32; o <<= 1) {
        int x = __shfl_up_sync(0xFFFFFFFFu, v, o);
        if (lane >= o) v += x;
    }
    if (lane == 31) warpsum[wid] = v;
    __syncthreads();
    if (wid == 0) {
        int w = warpsum[lane];
#pragma unroll
        for (int o = 1; o < 32; o <<= 1) {
            int x = __shfl_up_sync(0xFFFFFFFFu, w, o);
            if (lane >= o) w += x;
        }
        warpsum[lane] = w;
    }
    __syncthreads();
    int run = v - s + ((wid > 0) ? warpsum[wid - 1] : 0);
    for (int j = 0; j < SCHUNK; j++) {
        int i = base + j;
        if (i < NN) {
            int c = g_cnt[i];
            g_rowptr[i] = run;
            g_cursor[i] = run;
            run += c;
            g_dis[i] = rsqrtf((float)c + 1.0f);  // +1 self-loop
        }
    }
}

__global__ void k_fill(const int* __restrict__ ei) {
    int e = blockIdx.x * blockDim.x + threadIdx.x;
    if (e >= EE) return;
    int src = ei[e];
    int dst = ei[EE + e];
    int pos = atomicAdd(&g_cursor[dst], 1);
    g_epack[pos] = make_int2(src, __float_as_int(g_dis[src] * g_dis[dst]));
}

// ---------------- tensor-core GEMM (bf16 3-split, 3-image smem, 2 CTA/SM, PDL) ----------------
// smem: S0 = Whi ; S1 = Xhi ; S2 = Xlo (passes 1-2) then Wlo (pass 3)
// omode: 0 = store fp16 raw; 1 = relu(.+bias) fp16; 2 = relu(.+bias) + fused sigmoid head
// tmode: 0 identity, 1 relu(bn(v)), 2 bn(relu(v))
#define PADK 136
#define IMG (128 * PADK * 2)   // 34816
extern __shared__ char s_dyn[];

#define GEMM_PASS(aBase, wBase)                                                     \
    do {                                                                            \
        u32 aB = (aBase), wB = (wBase);                                             \
        _Pragma("unroll")                                                           \
        for (int ks = 0; ks < 8; ks++) {                                            \
            int kc = ks * 16;                                                       \
            u32 a[4][4], b[4][2];                                                   \
            _Pragma("unroll")                                                       \
            for (int mt = 0; mt < 4; mt++)                                          \
                ldsm_x4(a[mt][0], a[mt][1], a[mt][2], a[mt][3],                     \
                        aB + (u32)(((a_row + mt * 16) * PADK + kc + a_coff) * 2));  \
            _Pragma("unroll")                                                       \
            for (int nt = 0; nt < 4; nt++)                                          \
                ldsm_x2(b[nt][0], b[nt][1],                                         \
                        wB + (u32)(((b_row + nt * 8) * PADK + kc + b_coff) * 2));   \
            _Pragma("unroll")                                                       \
            for (int mt = 0; mt < 4; mt++)                                          \
                _Pragma("unroll")                                                   \
                for (int nt = 0; nt < 4; nt++)                                      \
                    mma16816(acc[mt][nt], a[mt], b[nt]);                            \
        }                                                                           \
    } while (0)

__global__ void __launch_bounds__(256, 2)
k_gemm_mma(const float* __restrict__ X, const __half* __restrict__ Xh,
           const u16* __restrict__ Wh, const u16* __restrict__ Wl,
           const float* __restrict__ bias, __half* __restrict__ Th,
           int n, int omode, int tmode,
           const float* __restrict__ gamma, const float* __restrict__ beta,
           const float* __restrict__ stats,
           const float* __restrict__ ow, const float* __restrict__ ob,
           float* __restrict__ dout) {
    __shared__ float s_scale[128], s_shift[128];
    __shared__ float s_part[128][4];
    char* sm = s_dyn;
    int t = threadIdx.x;
    int lane = t & 31, wid = t >> 5;
    int row0 = blockIdx.x * 128;

    // PDL window: for fp16-input layers the predecessor (gather/gemm) never writes
    // the weight images, so copy Whi into S0 BEFORE the dependency sync.
    bool early = (Xh != nullptr);
    if (early) {
#pragma unroll
        for (int i = 0; i < 8; i++) {
            int idx = i * 256 + t;
            int row = idx >> 4, c8 = idx & 15;
            *(float4*)(sm + row * PADK * 2 + c8 * 16) = ((const float4*)Wh)[idx];
        }
    }

    // wait for predecessor grids before touching data they wrote
    cudaGridDependencySynchronize();

    if (tmode && t < 128) {
        float inv = 1.0f / (float)NN;
        float mean = stats[t] * inv;
        float var = stats[128 + t] * inv - mean * mean;
        float rs = rsqrtf(var + BN_EPS);
        float sc = rs * gamma[t];
        s_scale[t] = sc;
        s_shift[t] = beta[t] - mean * sc;
    }
    __syncthreads();

    if (!early) {
        // gemm0: predecessor (prep_w) writes the weights -> copy after sync
#pragma unroll
        for (int i = 0; i < 8; i++) {
            int idx = i * 256 + t;
            int row = idx >> 4, c8 = idx & 15;
            *(float4*)(sm + row * PADK * 2 + c8 * 16) = ((const float4*)Wh)[idx];
        }
    }

    // X tile -> transform -> bf16 hi (S1) / lo (S2)
    if (Xh == nullptr) {
#pragma unroll
        for (int i = 0; i < 16; i++) {
            int idx = i * 256 + t;
            int row = idx >> 5;
            int c4 = idx & 31;
            int gr = row0 + row;
            float4 v = (gr < n) ? ((const float4*)X)[(size_t)gr * 32 + c4]
                                : make_float4(0.f, 0.f, 0.f, 0.f);
            float vv[4] = {v.x, v.y, v.z, v.w};
            u32 hw[2], lw[2];
#pragma unroll
            for (int j = 0; j < 2; j++) {
                __nv_bfloat16 h0 = __float2bfloat16_rn(vv[2 * j]);
                __nv_bfloat16 h1 = __float2bfloat16_rn(vv[2 * j + 1]);
                __nv_bfloat16 l0 = __float2bfloat16_rn(vv[2 * j] - __bfloat162float(h0));
                __nv_bfloat16 l1 = __float2bfloat16_rn(vv[2 * j + 1] - __bfloat162float(h1));
                hw[j] = ((u32)__bfloat16_as_ushort(h1) << 16) | __bfloat16_as_ushort(h0);
                lw[j] = ((u32)__bfloat16_as_ushort(l1) << 16) | __bfloat16_as_ushort(l0);
            }
            int off = row * PADK * 2 + c4 * 8;
            *(u32*)(sm + IMG + off) = hw[0];
            *(u32*)(sm + IMG + off + 4) = hw[1];
            *(u32*)(sm + 2 * IMG + off) = lw[0];
            *(u32*)(sm + 2 * IMG + off + 4) = lw[1];
        }
    } else {
#pragma unroll
        for (int i = 0; i < 8; i++) {
            int idx = i * 256 + t;       // uint4 index: 8 halves each
            int row = idx >> 4;
            int c8 = idx & 15;
            int gr = row0 + row;
            uint4 raw = make_uint4(0, 0, 0, 0);
            if (gr < n) raw = *(const uint4*)&Xh[(size_t)gr * 128 + c8 * 8];
            float f[8];
            float2 p;
            p = __half22float2(*(half2*)&raw.x); f[0] = p.x; f[1] = p.y;
            p = __half22float2(*(half2*)&raw.y); f[2] = p.x; f[3] = p.y;
            p = __half22float2(*(half2*)&raw.z); f[4] = p.x; f[5] = p.y;
            p = __half22float2(*(half2*)&raw.w); f[6] = p.x; f[7] = p.y;
            if (tmode) {
                int c0 = c8 * 8;
#pragma unroll
                for (int j = 0; j < 8; j++) {
                    float xv = f[j];
                    if (tmode == 2) xv = fmaxf(xv, 0.f);
                    float y = xv * s_scale[c0 + j] + s_shift[c0 + j];
                    if (tmode == 1) y = fmaxf(y, 0.f);
                    f[j] = y;
                }
            }
            u32 hw[4], lw[4];
#pragma unroll
            for (int j = 0; j < 4; j++) {
                __nv_bfloat16 h0 = __float2bfloat16_rn(f[2 * j]);
                __nv_bfloat16 h1 = __float2bfloat16_rn(f[2 * j + 1]);
                __nv_bfloat16 l0 = __float2bfloat16_rn(f[2 * j] - __bfloat162float(h0));
                __nv_bfloat16 l1 = __float2bfloat16_rn(f[2 * j + 1] - __bfloat162float(h1));
                hw[j] = ((u32)__bfloat16_as_ushort(h1) << 16) | __bfloat16_as_ushort(h0);
                lw[j] = ((u32)__bfloat16_as_ushort(l1) << 16) | __bfloat16_as_ushort(l0);
            }
            int off = row * PADK * 2 + c8 * 16;
            *(uint4*)(sm + IMG + off) = make_uint4(hw[0], hw[1], hw[2], hw[3]);
            *(uint4*)(sm + 2 * IMG + off) = make_uint4(lw[0], lw[1], lw[2], lw[3]);
        }
    }
    __syncthreads();

    int mw = wid >> 2, nw = wid & 3;
    float acc[4][4][4];
#pragma unroll
    for (int mt = 0; mt < 4; mt++)
#pragma unroll
        for (int nt = 0; nt < 4; nt++)
#pragma unroll
            for (int j = 0; j < 4; j++) acc[mt][nt][j] = 0.f;

    int a_row = mw * 64 + (lane & 15);
    int a_coff = (lane >> 4) * 8;
    int b_row = nw * 32 + (lane & 7);
    int b_coff = ((lane >> 3) & 1) * 8;

    u32 sS0 = su32(sm), sS1 = su32(sm + IMG), sS2 = su32(sm + 2 * IMG);

    GEMM_PASS(sS1, sS0);   // Xhi * Whi
    GEMM_PASS(sS2, sS0);   // Xlo * Whi
    __syncthreads();
    // overwrite S2 (Xlo, now dead) with Wlo
#pragma unroll
    for (int i = 0; i < 8; i++) {
        int idx = i * 256 + t;
        int row = idx >> 4, c8 = idx & 15;
        *(float4*)(sm + 2 * IMG + row * PADK * 2 + c8 * 16) = ((const float4*)Wl)[idx];
    }
    __syncthreads();
    GEMM_PASS(sS1, sS2);   // Xhi * Wlo

    // allow successor to begin launching while we run the epilogue
    cudaTriggerProgrammaticLaunchCompletion();

    // epilogue
    int g = lane >> 2, q = lane & 3;
#pragma unroll
    for (int mt = 0; mt < 4; mt++) {
        int rl1 = mw * 64 + mt * 16 + g;
        int r1 = row0 + rl1, r2 = r1 + 8;
        float p1 = 0.f, p2 = 0.f;
#pragma unroll
        for (int nt = 0; nt < 4; nt++) {
            int col = nw * 32 + nt * 8 + q * 2;
            float v0 = acc[mt][nt][0], v1 = acc[mt][nt][1];
            float v2 = acc[mt][nt][2], v3 = acc[mt][nt][3];
            if (omode >= 1) {
                float2 bb = *(const float2*)&bias[col];
                v0 = fmaxf(v0 + bb.x, 0.f); v1 = fmaxf(v1 + bb.y, 0.f);
                v2 = fmaxf(v2 + bb.x, 0.f); v3 = fmaxf(v3 + bb.y, 0.f);
            }
            if (omode <= 1) {
                if (r1 < n) *(half2*)&Th[(size_t)r1 * 128 + col] = __floats2half2_rn(v0, v1);
                if (r2 < n) *(half2*)&Th[(size_t)r2 * 128 + col] = __floats2half2_rn(v2, v3);
            } else {
                float w0 = __ldg(&ow[col]), w1 = __ldg(&ow[col + 1]);
                p1 += v0 * w0 + v1 * w1;
                p2 += v2 * w0 + v3 * w1;
            }
        }
        if (omode == 2) {
            p1 += __shfl_down_sync(0xFFFFFFFFu, p1, 1, 4);
            p1 += __shfl_down_sync(0xFFFFFFFFu, p1, 2, 4);
            p2 += __shfl_down_sync(0xFFFFFFFFu, p2, 1, 4);
            p2 += __shfl_down_sync(0xFFFFFFFFu, p2, 2, 4);
            if (q == 0) {
                s_part[rl1][nw] = p1;
                s_part[rl1 + 8][nw] = p2;
            }
        }
    }
    if (omode == 2) {
        __syncthreads();
        if (t < 128) {
            int gr = row0 + t;
            if (gr < n) {
                float s = s_part[t][0] + s_part[t][1] + s_part[t][2] + s_part[t][3] + ob[0];
                dout[gr] = 1.0f / (1.0f + expf(-s));
            }
        }
    }
}

// ---------------- CSR gather (fp16, dual-node 2+2 interleaved) + fused BN stats ----------------
__device__ __forceinline__ void acc_row4(const __half* __restrict__ Th, int src, float w,
                                         int lane, float* A) {
    uint2 u = *(const uint2*)&Th[(size_t)src * 128 + lane * 4];
    float2 a0 = __half22float2(*(half2*)&u.x);
    float2 a1 = __half22float2(*(half2*)&u.y);
    A[0] += w * a0.x; A[1] += w * a0.y; A[2] += w * a1.x; A[3] += w * a1.y;
}

__global__ void k_gather(const __half* __restrict__ Th, const float* __restrict__ bias,
                         __half* __restrict__ O, float* __restrict__ stats, int relu_first) {
    __shared__ float ss[8 * 128];
    __shared__ float sq[8 * 128];
    int t = threadIdx.x;
    int lane = t & 31, wid = t >> 5;
    int gw = blockIdx.x * 8 + wid;
    int tot = gridDim.x * 8;

    cudaGridDependencySynchronize();

    float4 b4 = ((const float4*)bias)[lane];
    float ls[4] = {0, 0, 0, 0};
    float lq[4] = {0, 0, 0, 0};

    for (int n1 = gw; n1 < NN; n1 += 2 * tot) {
        int n2 = n1 + tot;
        bool h2 = n2 < NN;
        float A[4] = {b4.x, b4.y, b4.z, b4.w};
        float B[4] = {b4.x, b4.y, b4.z, b4.w};
        float d1 = g_dis[n1];
        acc_row4(Th, n1, d1 * d1, lane, A);
        int i1 = g_rowptr[n1], e1 = i1 + g_cnt[n1];
        int i2 = 0, e2 = 0;
        if (h2) {
            float d2 = g_dis[n2];
            acc_row4(Th, n2, d2 * d2, lane, B);
            i2 = g_rowptr[n2];
            e2 = i2 + g_cnt[n2];
        }
        // interleaved 2+2: two independent dependency chains
        while (i1 + 1 < e1 && i2 + 1 < e2) {
            int2 pa = __ldg(&g_epack[i1]);
            int2 pb = __ldg(&g_epack[i1 + 1]);
            int2 pc = __ldg(&g_epack[i2]);
            int2 pd = __ldg(&g_epack[i2 + 1]);
            acc_row4(Th, pa.x, __int_as_float(pa.y), lane, A);
            acc_row4(Th, pc.x, __int_as_float(pc.y), lane, B);
            acc_row4(Th, pb.x, __int_as_float(pb.y), lane, A);
            acc_row4(Th, pd.x, __int_as_float(pd.y), lane, B);
            i1 += 2;
            i2 += 2;
        }
        for (; i1 + 3 < e1; i1 += 4) {
            int2 p0 = __ldg(&g_epack[i1]);
            int2 p1 = __ldg(&g_epack[i1 + 1]);
            int2 p2 = __ldg(&g_epack[i1 + 2]);
            int2 p3 = __ldg(&g_epack[i1 + 3]);
            acc_row4(Th, p0.x, __int_as_float(p0.y), lane, A);
            acc_row4(Th, p1.x, __int_as_float(p1.y), lane, A);
            acc_row4(Th, p2.x, __int_as_float(p2.y), lane, A);
            acc_row4(Th, p3.x, __int_as_float(p3.y), lane, A);
        }
        for (; i1 < e1; i1++) {
            int2 p0 = __ldg(&g_epack[i1]);
            acc_row4(Th, p0.x, __int_as_float(p0.y), lane, A);
        }
        for (; i2 + 3 < e2; i2 += 4) {
            int2 p0 = __ldg(&g_epack[i2]);
            int2 p1 = __ldg(&g_epack[i2 + 1]);
            int2 p2 = __ldg(&g_epack[i2 + 2]);
            int2 p3 = __ldg(&g_epack[i2 + 3]);
            acc_row4(Th, p0.x, __int_as_float(p0.y), lane, B);
            acc_row4(Th, p1.x, __int_as_float(p1.y), lane, B);
            acc_row4(Th, p2.x, __int_as_float(p2.y), lane, B);
            acc_row4(Th, p3.x, __int_as_float(p3.y), lane, B);
        }
        for (; i2 < e2; i2++) {
            int2 p0 = __ldg(&g_epack[i2]);
            acc_row4(Th, p0.x, __int_as_float(p0.y), lane, B);
        }
        // store + stats
        {
            half2 o0 = __floats2half2_rn(A[0], A[1]);
            half2 o1 = __floats2half2_rn(A[2], A[3]);
            uint2 ov;
            ov.x = *(u32*)&o0; ov.y = *(u32*)&o1;
            *(uint2*)&O[(size_t)n1 * 128 + lane * 4] = ov;
#pragma unroll
            for (int j = 0; j < 4; j++) {
                float r = relu_first ? fmaxf(A[j], 0.f) : A[j];
                ls[j] += r;
                lq[j] += r * r;
            }
        }
        if (h2) {
            half2 o0 = __floats2half2_rn(B[0], B[1]);
            half2 o1 = __floats2half2_rn(B[2], B[3]);
            uint2 ov;
            ov.x = *(u32*)&o0; ov.y = *(u32*)&o1;
            *(uint2*)&O[(size_t)n2 * 128 + lane * 4] = ov;
#pragma unroll
            for (int j = 0; j < 4; j++) {
                float r = relu_first ? fmaxf(B[j], 0.f) : B[j];
                ls[j] += r;
                lq[j] += r * r;
            }
        }
    }

    cudaTriggerProgrammaticLaunchCompletion();

    float* ps = &ss[wid * 128 + lane * 4];
    float* pq = &sq[wid * 128 + lane * 4];
#pragma unroll
    for (int j = 0; j < 4; j++) {
        ps[j] = ls[j];
        pq[j] = lq[j];
    }
    __syncthreads();
    if (t < 128) {
        float a = 0.f, b = 0.f;
#pragma unroll
        for (int w = 0; w < 8; w++) {
            a += ss[w * 128 + t];
            b += sq[w * 128 + t];
        }
        atomicAdd(&stats[t], a);
        atomicAdd(&stats[128 + t], b);
    }
}

// ---------------- launch ----------------
extern "C" void kernel_launch(void* const* d_in, const int* in_sizes, int n_in,
                              void* d_out, int out_size) {
    const float *x = nullptr, *conv_w = nullptr, *conv_b = nullptr;
    const float *bn_g = nullptr, *bn_b = nullptr, *mlp_w = nullptr, *mlp_b = nullptr;
    const float *out_w = nullptr, *out_b = nullptr;
    const int* ei = nullptr;
    int n256 = 0;
    for (int i = 0; i < n_in; i++) {
        switch (in_sizes[i]) {
            case 6400000: x = (const float*)d_in[i]; break;
            case 1600000: ei = (const int*)d_in[i]; break;
            case 49152:   conv_w = (const float*)d_in[i]; break;
            case 384:     conv_b = (const float*)d_in[i]; break;
            case 32768:   mlp_w = (const float*)d_in[i]; break;
            case 128:     out_w = (const float*)d_in[i]; break;
            case 1:       out_b = (const float*)d_in[i]; break;
            case 256:
                if (n256 == 0) bn_g = (const float*)d_in[i];
                else if (n256 == 1) bn_b = (const float*)d_in[i];
                else mlp_b = (const float*)d_in[i];
                n256++;
                break;
            default: break;
        }
    }

    __half *bufH, *bufTh;
    float* stats;
    u16 *whi, *wlo;
    cudaGetSymbolAddress((void**)&bufH, g_bufH);
    cudaGetSymbolAddress((void**)&bufTh, g_bufTh);
    cudaGetSymbolAddress((void**)&whi, g_whi);
    cudaGetSymbolAddress((void**)&wlo, g_wlo);
    cudaGetSymbolAddress((void**)&stats, g_stats3);

    const int SMEM = 3 * IMG;  // 104448 -> 2 CTAs/SM
    cudaFuncSetAttribute(k_gemm_mma, cudaFuncAttributeMaxDynamicSharedMemorySize, SMEM);

    const int GB = (NN + 127) / 128;  // 391
    const int EB = (EE + 255) / 256;

    // one-time side stream + events (created once; capture-safe fork/join)
    static cudaStream_t s1 = nullptr;
    static cudaEvent_t evRoot = nullptr, evJoin = nullptr;
    if (s1 == nullptr) {
        cudaStreamCreateWithFlags(&s1, cudaStreamNonBlocking);
        cudaEventCreateWithFlags(&evRoot, cudaEventDisableTiming);
        cudaEventCreateWithFlags(&evJoin, cudaEventDisableTiming);
    }

    // PDL launch configs
    cudaLaunchAttribute pdlAttr[1];
    pdlAttr[0].id = cudaLaunchAttributeProgrammaticStreamSerialization;
    pdlAttr[0].val.programmaticStreamSerializationAllowed = 1;

    cudaLaunchConfig_t cfgGemm = {};
    cfgGemm.gridDim = dim3(GB);
    cfgGemm.blockDim = dim3(256);
    cfgGemm.dynamicSmemBytes = SMEM;
    cfgGemm.stream = 0;
    cfgGemm.attrs = pdlAttr;
    cfgGemm.numAttrs = 1;

    cudaLaunchConfig_t cfgGather = {};
    cfgGather.gridDim = dim3(1184);
    cfgGather.blockDim = dim3(256);
    cfgGather.dynamicSmemBytes = 0;
    cfgGather.stream = 0;
    cfgGather.attrs = pdlAttr;
    cfgGather.numAttrs = 1;

    const __half* nullH = nullptr;
    const float* nullF = nullptr;
    float* nullFo = nullptr;

    // prep first (zeroes cnt/stats + weight split) on main stream
    k_prep_w<<<(5 * 16384 + 255) / 256, 256>>>(conv_w, mlp_w);
    cudaEventRecord(evRoot, 0);
    cudaStreamWaitEvent(s1, evRoot, 0);

    // CSR chain on s1 (3 kernels)
    k_hist<<<EB, 256, 0, s1>>>(ei);
    k_scan1<<<1, 1024, 0, s1>>>();
    k_fill<<<EB, 256, 0, s1>>>(ei);
    cudaEventRecord(evJoin, s1);

    // gemm0 on main (overlaps CSR build)
    cudaLaunchKernelEx(&cfgGemm, k_gemm_mma,
                       x, nullH, (const u16*)whi, (const u16*)wlo, nullF, bufTh,
                       (int)NN, 0, 0, nullF, nullF, nullF, nullF, nullF, nullFo);

    cudaStreamWaitEvent(0, evJoin, 0);  // join before gather0

    // layer 0
    cudaLaunchKernelEx(&cfgGather, k_gather,
                       (const __half*)bufTh, conv_b, bufH, stats, 0);

    // layer 1
    cudaLaunchKernelEx(&cfgGemm, k_gemm_mma,
                       nullF, (const __half*)bufH, (const u16*)(whi + 16384), (const u16*)(wlo + 16384),
                       nullF, bufTh, (int)NN, 0, 1, bn_g, bn_b, (const float*)stats,
                       nullF, nullF, nullFo);
    cudaLaunchKernelEx(&cfgGather, k_gather,
                       (const __half*)bufTh, conv_b + 128, bufH, stats + 256, 0);

    // layer 2
    cudaLaunchKernelEx(&cfgGemm, k_gemm_mma,
                       nullF, (const __half*)bufH, (const u16*)(whi + 32768), (const u16*)(wlo + 32768),
                       nullF, bufTh, (int)NN, 0, 1, bn_g + 128, bn_b + 128, (const float*)(stats + 256),
                       nullF, nullF, nullFo);
    cudaLaunchKernelEx(&cfgGather, k_gather,
                       (const __half*)bufTh, conv_b + 256, bufH, stats + 512, 1);

    // mlp1: tmode 2 (bn1(relu(h2)) quirk), relu(+bias) -> fp16 bufTh
    cudaLaunchKernelEx(&cfgGemm, k_gemm_mma,
                       nullF, (const __half*)bufH, (const u16*)(whi + 49152), (const u16*)(wlo + 49152),
                       mlp_b, bufTh, (int)NN, 1, 2, bn_g + 128, bn_b + 128, (const float*)(stats + 512),
                       nullF, nullF, nullFo);
    // mlp2 + fused sigmoid head
    cudaLaunchKernelEx(&cfgGemm, k_gemm_mma,
                       nullF, (const __half*)bufTh, (const u16*)(whi + 65536), (const u16*)(wlo + 65536),
                       mlp_b + 128, (__half*)nullptr, (int)NN, 2, 0, nullF, nullF, nullF,
                       out_w, out_b, (float*)d_out);
}

// round 15
// speedup vs baseline: 1.3784x; 1.3784x over previous
#include <cuda_runtime.h>
#include <cuda_bf16.h>
#include <cuda_fp16.h>
#include <math.h>

#define NN 50000
#define EE 800000
#define DD 128
#define BN_EPS 1e-5f
#define SCAN_NT ((NN + 127) / 128)   // 391

typedef unsigned long long u64;
typedef unsigned int u32;
typedef unsigned short u16;

// ---------------- scratch (no allocs allowed) ----------------
__device__ __half g_bufH[NN * DD];    // activations (gather out / gemm in)
__device__ __half g_bufTh[NN * DD];   // transformed messages (gemm out / gather in)
__device__ float  g_dis[NN];
__device__ float  g_stats3[3 * 256];
__device__ int    g_cnt[NN];
__device__ int    g_rowptr[NN];
__device__ int    g_cursor[NN];
__device__ int2   g_epack[EE];        // (src, bitcast(w))
__device__ int    g_tsum[512];
__device__ u16    g_whi[5 * 16384];
__device__ u16    g_wlo[5 * 16384];

// ---------------- mma helpers ----------------
__device__ __forceinline__ u32 su32(const void* p) {
    return (u32)__cvta_generic_to_shared(p);
}
__device__ __forceinline__ void ldsm_x4(u32& r0, u32& r1, u32& r2, u32& r3, u32 addr) {
    asm volatile("ldmatrix.sync.aligned.m8n8.x4.shared.b16 {%0,%1,%2,%3}, [%4];"
                 : "=r"(r0), "=r"(r1), "=r"(r2), "=r"(r3) : "r"(addr));
}
__device__ __forceinline__ void ldsm_x2(u32& r0, u32& r1, u32 addr) {
    asm volatile("ldmatrix.sync.aligned.m8n8.x2.shared.b16 {%0,%1}, [%2];"
                 : "=r"(r0), "=r"(r1) : "r"(addr));
}
__device__ __forceinline__ void mma16816(float* c, const u32* a, const u32* b) {
    asm volatile(
        "mma.sync.aligned.m16n8k16.row.col.f32.bf16.bf16.f32 "
        "{%0,%1,%2,%3}, {%4,%5,%6,%7}, {%8,%9}, {%0,%1,%2,%3};"
        : "+f"(c[0]), "+f"(c[1]), "+f"(c[2]), "+f"(c[3])
        : "r"(a[0]), "r"(a[1]), "r"(a[2]), "r"(a[3]), "r"(b[0]), "r"(b[1]));
}

// ---------------- weight prep (+ zero stats) ----------------
__global__ void k_prep_w(const float* __restrict__ conv_w, const float* __restrict__ mlp_w) {
    int idx = blockIdx.x * blockDim.x + threadIdx.x;
    if (idx < 3 * 256) g_stats3[idx] = 0.f;
    if (idx >= 5 * 16384) return;
    int w = idx >> 14;
    int r = idx & 16383;
    int fout = r >> 7;
    int k = r & 127;
    float v = (w < 3) ? conv_w[w * 16384 + k * 128 + fout]
                      : mlp_w[(w - 3) * 16384 + k * 128 + fout];
    __nv_bfloat16 hi = __float2bfloat16_rn(v);
    __nv_bfloat16 lo = __float2bfloat16_rn(v - __bfloat162float(hi));
    g_whi[idx] = __bfloat16_as_ushort(hi);   // [w][fout][k]
    g_wlo[idx] = __bfloat16_as_ushort(lo);
}

// ---------------- CSR build ----------------
__global__ void k_zero_cnt() {
    int i = blockIdx.x * blockDim.x + threadIdx.x;
    if (i < NN) g_cnt[i] = 0;
}
// histogram over edge range [e0, e0+cnt)
__global__ void k_hist(const int* __restrict__ ei, int e0, int cnt) {
    int e = blockIdx.x * blockDim.x + threadIdx.x;
    if (e < cnt) atomicAdd(&g_cnt[ei[EE + e0 + e]], 1);
}
// tile sums + deg norm
__global__ void k_scanA() {
    __shared__ int sh[4];
    int t = threadIdx.x;
    int i = blockIdx.x * 128 + t;
    int c = (i < NN) ? g_cnt[i] : 0;
    if (i < NN) g_dis[i] = rsqrtf((float)c + 1.0f);  // +1 self-loop
    int v = c;
#pragma unroll
    for (int o = 16; o; o >>= 1) v += __shfl_down_sync(0xFFFFFFFFu, v, o);
    if ((t & 31) == 0) sh[t >> 5] = v;
    __syncthreads();
    if (t == 0) g_tsum[blockIdx.x] = sh[0] + sh[1] + sh[2] + sh[3];
}
// per-tile scan via warp shuffles + cross-tile base (merged scanB)
__global__ void k_scanC() {
    __shared__ int swarp[4];
    __shared__ int sbase[4];
    int t = threadIdx.x;
    int lane = t & 31, wid = t >> 5;
    int part = 0;
    for (int j = t; j < blockIdx.x; j += 128) part += g_tsum[j];
#pragma unroll
    for (int o = 16; o; o >>= 1) part += __shfl_down_sync(0xFFFFFFFFu, part, o);
    if (lane == 0) sbase[wid] = part;
    int i = blockIdx.x * 128 + t;
    int v = (i < NN) ? g_cnt[i] : 0;
    int inc = v;
#pragma unroll
    for (int o = 1; o < 32; o <<= 1) {
        int x = __shfl_up_sync(0xFFFFFFFFu, inc, o);
        if (lane >= o) inc += x;
    }
    if (lane == 31) swarp[wid] = inc;
    __syncthreads();
    int base = sbase[0] + sbase[1] + sbase[2] + sbase[3];
    int woff = 0;
#pragma unroll
    for (int w = 0; w < 4; w++)
        if (w < wid) woff += swarp[w];
    if (i < NN) {
        int ex = base + woff + inc - v;   // exclusive
        g_rowptr[i] = ex;
        g_cursor[i] = ex;
    }
}
// fill over edge range [e0, e0+cnt)
__global__ void k_fill(const int* __restrict__ ei, int e0, int cnt) {
    int e = blockIdx.x * blockDim.x + threadIdx.x;
    if (e >= cnt) return;
    int src = ei[e0 + e];
    int dst = ei[EE + e0 + e];
    int pos = atomicAdd(&g_cursor[dst], 1);
    g_epack[pos] = make_int2(src, __float_as_int(g_dis[src] * g_dis[dst]));
}

// ---------------- tensor-core GEMM (bf16 3-split, 3-image smem, 2 CTA/SM, PDL) ----------------
// smem: S0 = Whi ; S1 = Xhi ; S2 = Xlo (passes 1-2) then Wlo (pass 3)
// omode: 0 = store fp16 raw; 1 = relu(.+bias) fp16; 2 = relu(.+bias) + fused sigmoid head
// tmode: 0 identity, 1 relu(bn(v)), 2 bn(relu(v))
#define PADK 136
#define IMG (128 * PADK * 2)   // 34816
extern __shared__ char s_dyn[];

#define GEMM_PASS(aBase, wBase)                                                     \
    do {                                                                            \
        u32 aB = (aBase), wB = (wBase);                                             \
        _Pragma("unroll")                                                           \
        for (int ks = 0; ks < 8; ks++) {                                            \
            int kc = ks * 16;                                                       \
            u32 a[4][4], b[4][2];                                                   \
            _Pragma("unroll")                                                       \
            for (int mt = 0; mt < 4; mt++)                                          \
                ldsm_x4(a[mt][0], a[mt][1], a[mt][2], a[mt][3],                     \
                        aB + (u32)(((a_row + mt * 16) * PADK + kc + a_coff) * 2));  \
            _Pragma("unroll")                                                       \
            for (int nt = 0; nt < 4; nt++)                                          \
                ldsm_x2(b[nt][0], b[nt][1],                                         \
                        wB + (u32)(((b_row + nt * 8) * PADK + kc + b_coff) * 2));   \
            _Pragma("unroll")                                                       \
            for (int mt = 0; mt < 4; mt++)                                          \
                _Pragma("unroll")                                                   \
                for (int nt = 0; nt < 4; nt++)                                      \
                    mma16816(acc[mt][nt], a[mt], b[nt]);                            \
        }                                                                           \
    } while (0)

__global__ void __launch_bounds__(256, 2)
k_gemm_mma(const float* __restrict__ X, const __half* __restrict__ Xh,
           const u16* __restrict__ Wh, const u16* __restrict__ Wl,
           const float* __restrict__ bias, __half* __restrict__ Th,
           int n, int omode, int tmode,
           const float* __restrict__ gamma, const float* __restrict__ beta,
           const float* __restrict__ stats,
           const float* __restrict__ ow, const float* __restrict__ ob,
           float* __restrict__ dout) {
    __shared__ float s_scale[128], s_shift[128];
    __shared__ float s_part[128][4];
    char* sm = s_dyn;
    int t = threadIdx.x;
    int lane = t & 31, wid = t >> 5;
    int row0 = blockIdx.x * 128;

    // wait for predecessor grids before touching any global data they wrote
    cudaGridDependencySynchronize();

    if (tmode && t < 128) {
        float inv = 1.0f / (float)NN;
        float mean = stats[t] * inv;
        float var = stats[128 + t] * inv - mean * mean;
        float rs = rsqrtf(var + BN_EPS);
        float sc = rs * gamma[t];
        s_scale[t] = sc;
        s_shift[t] = beta[t] - mean * sc;
    }
    __syncthreads();

    // Whi image into S0
#pragma unroll
    for (int i = 0; i < 8; i++) {
        int idx = i * 256 + t;
        int row = idx >> 4, c8 = idx & 15;
        *(float4*)(sm + row * PADK * 2 + c8 * 16) = ((const float4*)Wh)[idx];
    }

    // X tile -> transform -> bf16 hi (S1) / lo (S2)
    if (Xh == nullptr) {
#pragma unroll
        for (int i = 0; i < 16; i++) {
            int idx = i * 256 + t;
            int row = idx >> 5;
            int c4 = idx & 31;
            int gr = row0 + row;
            float4 v = (gr < n) ? ((const float4*)X)[(size_t)gr * 32 + c4]
                                : make_float4(0.f, 0.f, 0.f, 0.f);
            float vv[4] = {v.x, v.y, v.z, v.w};
            u32 hw[2], lw[2];
#pragma unroll
            for (int j = 0; j < 2; j++) {
                __nv_bfloat16 h0 = __float2bfloat16_rn(vv[2 * j]);
                __nv_bfloat16 h1 = __float2bfloat16_rn(vv[2 * j + 1]);
                __nv_bfloat16 l0 = __float2bfloat16_rn(vv[2 * j] - __bfloat162float(h0));
                __nv_bfloat16 l1 = __float2bfloat16_rn(vv[2 * j + 1] - __bfloat162float(h1));
                hw[j] = ((u32)__bfloat16_as_ushort(h1) << 16) | __bfloat16_as_ushort(h0);
                lw[j] = ((u32)__bfloat16_as_ushort(l1) << 16) | __bfloat16_as_ushort(l0);
            }
            int off = row * PADK * 2 + c4 * 8;
            *(u32*)(sm + IMG + off) = hw[0];
            *(u32*)(sm + IMG + off + 4) = hw[1];
            *(u32*)(sm + 2 * IMG + off) = lw[0];
            *(u32*)(sm + 2 * IMG + off + 4) = lw[1];
        }
    } else {
#pragma unroll
        for (int i = 0; i < 8; i++) {
            int idx = i * 256 + t;       // uint4 index: 8 halves each
            int row = idx >> 4;
            int c8 = idx & 15;
            int gr = row0 + row;
            uint4 raw = make_uint4(0, 0, 0, 0);
            if (gr < n) raw = *(const uint4*)&Xh[(size_t)gr * 128 + c8 * 8];
            float f[8];
            float2 p;
            p = __half22float2(*(half2*)&raw.x); f[0] = p.x; f[1] = p.y;
            p = __half22float2(*(half2*)&raw.y); f[2] = p.x; f[3] = p.y;
            p = __half22float2(*(half2*)&raw.z); f[4] = p.x; f[5] = p.y;
            p = __half22float2(*(half2*)&raw.w); f[6] = p.x; f[7] = p.y;
            if (tmode) {
                int c0 = c8 * 8;
#pragma unroll
                for (int j = 0; j < 8; j++) {
                    float xv = f[j];
                    if (tmode == 2) xv = fmaxf(xv, 0.f);
                    float y = xv * s_scale[c0 + j] + s_shift[c0 + j];
                    if (tmode == 1) y = fmaxf(y, 0.f);
                    f[j] = y;
                }
            }
            u32 hw[4], lw[4];
#pragma unroll
            for (int j = 0; j < 4; j++) {
                __nv_bfloat16 h0 = __float2bfloat16_rn(f[2 * j]);
                __nv_bfloat16 h1 = __float2bfloat16_rn(f[2 * j + 1]);
                __nv_bfloat16 l0 = __float2bfloat16_rn(f[2 * j] - __bfloat162float(h0));
                __nv_bfloat16 l1 = __float2bfloat16_rn(f[2 * j + 1] - __bfloat162float(h1));
                hw[j] = ((u32)__bfloat16_as_ushort(h1) << 16) | __bfloat16_as_ushort(h0);
                lw[j] = ((u32)__bfloat16_as_ushort(l1) << 16) | __bfloat16_as_ushort(l0);
            }
            int off = row * PADK * 2 + c8 * 16;
            *(uint4*)(sm + IMG + off) = make_uint4(hw[0], hw[1], hw[2], hw[3]);
            *(uint4*)(sm + 2 * IMG + off) = make_uint4(lw[0], lw[1], lw[2], lw[3]);
        }
    }
    __syncthreads();

    int mw = wid >> 2, nw = wid & 3;
    float acc[4][4][4];
#pragma unroll
    for (int mt = 0; mt < 4; mt++)
#pragma unroll
        for (int nt = 0; nt < 4; nt++)
#pragma unroll
            for (int j = 0; j < 4; j++) acc[mt][nt][j] = 0.f;

    int a_row = mw * 64 + (lane & 15);
    int a_coff = (lane >> 4) * 8;
    int b_row = nw * 32 + (lane & 7);
    int b_coff = ((lane >> 3) & 1) * 8;

    u32 sS0 = su32(sm), sS1 = su32(sm + IMG), sS2 = su32(sm + 2 * IMG);

    GEMM_PASS(sS1, sS0);   // Xhi * Whi
    GEMM_PASS(sS2, sS0);   // Xlo * Whi
    __syncthreads();
    // overwrite S2 (Xlo, now dead) with Wlo
#pragma unroll
    for (int i = 0; i < 8; i++) {
        int idx = i * 256 + t;
        int row = idx >> 4, c8 = idx & 15;
        *(float4*)(sm + 2 * IMG + row * PADK * 2 + c8 * 16) = ((const float4*)Wl)[idx];
    }
    __syncthreads();
    GEMM_PASS(sS1, sS2);   // Xhi * Wlo

    // allow successor to begin launching while we run the epilogue
    cudaTriggerProgrammaticLaunchCompletion();

    // epilogue
    int g = lane >> 2, q = lane & 3;
#pragma unroll
    for (int mt = 0; mt < 4; mt++) {
        int rl1 = mw * 64 + mt * 16 + g;
        int r1 = row0 + rl1, r2 = r1 + 8;
        float p1 = 0.f, p2 = 0.f;
#pragma unroll
        for (int nt = 0; nt < 4; nt++) {
            int col = nw * 32 + nt * 8 + q * 2;
            float v0 = acc[mt][nt][0], v1 = acc[mt][nt][1];
            float v2 = acc[mt][nt][2], v3 = acc[mt][nt][3];
            if (omode >= 1) {
                float2 bb = *(const float2*)&bias[col];
                v0 = fmaxf(v0 + bb.x, 0.f); v1 = fmaxf(v1 + bb.y, 0.f);
                v2 = fmaxf(v2 + bb.x, 0.f); v3 = fmaxf(v3 + bb.y, 0.f);
            }
            if (omode <= 1) {
                if (r1 < n) *(half2*)&Th[(size_t)r1 * 128 + col] = __floats2half2_rn(v0, v1);
                if (r2 < n) *(half2*)&Th[(size_t)r2 * 128 + col] = __floats2half2_rn(v2, v3);
            } else {
                float w0 = __ldg(&ow[col]), w1 = __ldg(&ow[col + 1]);
                p1 += v0 * w0 + v1 * w1;
                p2 += v2 * w0 + v3 * w1;
            }
        }
        if (omode == 2) {
            p1 += __shfl_down_sync(0xFFFFFFFFu, p1, 1, 4);
            p1 += __shfl_down_sync(0xFFFFFFFFu, p1, 2, 4);
            p2 += __shfl_down_sync(0xFFFFFFFFu, p2, 1, 4);
            p2 += __shfl_down_sync(0xFFFFFFFFu, p2, 2, 4);
            if (q == 0) {
                s_part[rl1][nw] = p1;
                s_part[rl1 + 8][nw] = p2;
            }
        }
    }
    if (omode == 2) {
        __syncthreads();
        if (t < 128) {
            int gr = row0 + t;
            if (gr < n) {
                float s = s_part[t][0] + s_part[t][1] + s_part[t][2] + s_part[t][3] + ob[0];
                dout[gr] = 1.0f / (1.0f + expf(-s));
            }
        }
    }
}

// ---------------- CSR gather (fp16, dual-node 2+2 interleaved) + fused BN stats ----------------
__device__ __forceinline__ void acc_row4(const __half* __restrict__ Th, int src, float w,
                                         int lane, float* A) {
    uint2 u = *(const uint2*)&Th[(size_t)src * 128 + lane * 4];
    float2 a0 = __half22float2(*(half2*)&u.x);
    float2 a1 = __half22float2(*(half2*)&u.y);
    A[0] += w * a0.x; A[1] += w * a0.y; A[2] += w * a1.x; A[3] += w * a1.y;
}

__global__ void k_gather(const __half* __restrict__ Th, const float* __restrict__ bias,
                         __half* __restrict__ O, float* __restrict__ stats, int relu_first) {
    __shared__ float ss[8 * 128];
    __shared__ float sq[8 * 128];
    int t = threadIdx.x;
    int lane = t & 31, wid = t >> 5;
    int gw = blockIdx.x * 8 + wid;
    int tot = gridDim.x * 8;

    cudaGridDependencySynchronize();

    float4 b4 = ((const float4*)bias)[lane];
    float ls[4] = {0, 0, 0, 0};
    float lq[4] = {0, 0, 0, 0};

    for (int n1 = gw; n1 < NN; n1 += 2 * tot) {
        int n2 = n1 + tot;
        bool h2 = n2 < NN;
        float A[4] = {b4.x, b4.y, b4.z, b4.w};
        float B[4] = {b4.x, b4.y, b4.z, b4.w};
        float d1 = g_dis[n1];
        acc_row4(Th, n1, d1 * d1, lane, A);
        int i1 = g_rowptr[n1], e1 = i1 + g_cnt[n1];
        int i2 = 0, e2 = 0;
        if (h2) {
            float d2 = g_dis[n2];
            acc_row4(Th, n2, d2 * d2, lane, B);
            i2 = g_rowptr[n2];
            e2 = i2 + g_cnt[n2];
        }
        // interleaved 2+2: two independent dependency chains
        while (i1 + 1 < e1 && i2 + 1 < e2) {
            int2 pa = __ldg(&g_epack[i1]);
            int2 pb = __ldg(&g_epack[i1 + 1]);
            int2 pc = __ldg(&g_epack[i2]);
            int2 pd = __ldg(&g_epack[i2 + 1]);
            acc_row4(Th, pa.x, __int_as_float(pa.y), lane, A);
            acc_row4(Th, pc.x, __int_as_float(pc.y), lane, B);
            acc_row4(Th, pb.x, __int_as_float(pb.y), lane, A);
            acc_row4(Th, pd.x, __int_as_float(pd.y), lane, B);
            i1 += 2;
            i2 += 2;
        }
        for (; i1 + 3 < e1; i1 += 4) {
            int2 p0 = __ldg(&g_epack[i1]);
            int2 p1 = __ldg(&g_epack[i1 + 1]);
            int2 p2 = __ldg(&g_epack[i1 + 2]);
            int2 p3 = __ldg(&g_epack[i1 + 3]);
            acc_row4(Th, p0.x, __int_as_float(p0.y), lane, A);
            acc_row4(Th, p1.x, __int_as_float(p1.y), lane, A);
            acc_row4(Th, p2.x, __int_as_float(p2.y), lane, A);
            acc_row4(Th, p3.x, __int_as_float(p3.y), lane, A);
        }
        for (; i1 < e1; i1++) {
            int2 p0 = __ldg(&g_epack[i1]);
            acc_row4(Th, p0.x, __int_as_float(p0.y), lane, A);
        }
        for (; i2 + 3 < e2; i2 += 4) {
            int2 p0 = __ldg(&g_epack[i2]);
            int2 p1 = __ldg(&g_epack[i2 + 1]);
            int2 p2 = __ldg(&g_epack[i2 + 2]);
            int2 p3 = __ldg(&g_epack[i2 + 3]);
            acc_row4(Th, p0.x, __int_as_float(p0.y), lane, B);
            acc_row4(Th, p1.x, __int_as_float(p1.y), lane, B);
            acc_row4(Th, p2.x, __int_as_float(p2.y), lane, B);
            acc_row4(Th, p3.x, __int_as_float(p3.y), lane, B);
        }
        for (; i2 < e2; i2++) {
            int2 p0 = __ldg(&g_epack[i2]);
            acc_row4(Th, p0.x, __int_as_float(p0.y), lane, B);
        }
        // store + stats
        {
            half2 o0 = __floats2half2_rn(A[0], A[1]);
            half2 o1 = __floats2half2_rn(A[2], A[3]);
            uint2 ov;
            ov.x = *(u32*)&o0; ov.y = *(u32*)&o1;
            *(uint2*)&O[(size_t)n1 * 128 + lane * 4] = ov;
#pragma unroll
            for (int j = 0; j < 4; j++) {
                float r = relu_first ? fmaxf(A[j], 0.f) : A[j];
                ls[j] += r;
                lq[j] += r * r;
            }
        }
        if (h2) {
            half2 o0 = __floats2half2_rn(B[0], B[1]);
            half2 o1 = __floats2half2_rn(B[2], B[3]);
            uint2 ov;
            ov.x = *(u32*)&o0; ov.y = *(u32*)&o1;
            *(uint2*)&O[(size_t)n2 * 128 + lane * 4] = ov;
#pragma unroll
            for (int j = 0; j < 4; j++) {
                float r = relu_first ? fmaxf(B[j], 0.f) : B[j];
                ls[j] += r;
                lq[j] += r * r;
            }
        }
    }

    cudaTriggerProgrammaticLaunchCompletion();

    float* ps = &ss[wid * 128 + lane * 4];
    float* pq = &sq[wid * 128 + lane * 4];
#pragma unroll
    for (int j = 0; j < 4; j++) {
        ps[j] = ls[j];
        pq[j] = lq[j];
    }
    __syncthreads();
    if (t < 128) {
        float a = 0.f, b = 0.f;
#pragma unroll
        for (int w = 0; w < 8; w++) {
            a += ss[w * 128 + t];
            b += sq[w * 128 + t];
        }
        atomicAdd(&stats[t], a);
        atomicAdd(&stats[128 + t], b);
    }
}

// ---------------- launch ----------------
extern "C" void kernel_launch(void* const* d_in, const int* in_sizes, int n_in,
                              void* d_out, int out_size) {
    const float *x = nullptr, *conv_w = nullptr, *conv_b = nullptr;
    const float *bn_g = nullptr, *bn_b = nullptr, *mlp_w = nullptr, *mlp_b = nullptr;
    const float *out_w = nullptr, *out_b = nullptr;
    const int* ei = nullptr;
    int n256 = 0;
    for (int i = 0; i < n_in; i++) {
        switch (in_sizes[i]) {
            case 6400000: x = (const float*)d_in[i]; break;
            case 1600000: ei = (const int*)d_in[i]; break;
            case 49152:   conv_w = (const float*)d_in[i]; break;
            case 384:     conv_b = (const float*)d_in[i]; break;
            case 32768:   mlp_w = (const float*)d_in[i]; break;
            case 128:     out_w = (const float*)d_in[i]; break;
            case 1:       out_b = (const float*)d_in[i]; break;
            case 256:
                if (n256 == 0) bn_g = (const float*)d_in[i];
                else if (n256 == 1) bn_b = (const float*)d_in[i];
                else mlp_b = (const float*)d_in[i];
                n256++;
                break;
            default: break;
        }
    }

    __half *bufH, *bufTh;
    float* stats;
    u16 *whi, *wlo;
    cudaGetSymbolAddress((void**)&bufH, g_bufH);
    cudaGetSymbolAddress((void**)&bufTh, g_bufTh);
    cudaGetSymbolAddress((void**)&whi, g_whi);
    cudaGetSymbolAddress((void**)&wlo, g_wlo);
    cudaGetSymbolAddress((void**)&stats, g_stats3);

    const int SMEM = 3 * IMG;  // 104448 -> 2 CTAs/SM
    cudaFuncSetAttribute(k_gemm_mma, cudaFuncAttributeMaxDynamicSharedMemorySize, SMEM);

    const int GB = (NN + 127) / 128;  // 391
    const int NB = (NN + 255) / 256;
    const int EH = EE / 2;                 // 400000 per half
    const int EBH = (EH + 255) / 256;      // 1563

    // one-time side streams + events (created once; capture-safe fork/join)
    static cudaStream_t s1 = nullptr, s2 = nullptr;
    static cudaEvent_t evRoot = nullptr, evZ = nullptr, evH = nullptr,
                       evS = nullptr, evJ1 = nullptr, evJ2 = nullptr;
    if (s1 == nullptr) {
        cudaStreamCreateWithFlags(&s1, cudaStreamNonBlocking);
        cudaStreamCreateWithFlags(&s2, cudaStreamNonBlocking);
        cudaEventCreateWithFlags(&evRoot, cudaEventDisableTiming);
        cudaEventCreateWithFlags(&evZ, cudaEventDisableTiming);
        cudaEventCreateWithFlags(&evH, cudaEventDisableTiming);
        cudaEventCreateWithFlags(&evS, cudaEventDisableTiming);
        cudaEventCreateWithFlags(&evJ1, cudaEventDisableTiming);
        cudaEventCreateWithFlags(&evJ2, cudaEventDisableTiming);
    }

    // PDL launch configs
    cudaLaunchAttribute pdlAttr[1];
    pdlAttr[0].id = cudaLaunchAttributeProgrammaticStreamSerialization;
    pdlAttr[0].val.programmaticStreamSerializationAllowed = 1;

    cudaLaunchConfig_t cfgGemm = {};
    cfgGemm.gridDim = dim3(GB);
    cfgGemm.blockDim = dim3(256);
    cfgGemm.dynamicSmemBytes = SMEM;
    cfgGemm.stream = 0;
    cfgGemm.attrs = pdlAttr;
    cfgGemm.numAttrs = 1;

    cudaLaunchConfig_t cfgGather = {};
    cfgGather.gridDim = dim3(1184);
    cfgGather.blockDim = dim3(256);
    cfgGather.dynamicSmemBytes = 0;
    cfgGather.stream = 0;
    cfgGather.attrs = pdlAttr;
    cfgGather.numAttrs = 1;

    const __half* nullH = nullptr;
    const float* nullF = nullptr;
    float* nullFo = nullptr;

    // fork: CSR build on s1+s2, weight prep + gemm0 on main stream
    cudaEventRecord(evRoot, 0);
    cudaStreamWaitEvent(s1, evRoot, 0);
    cudaStreamWaitEvent(s2, evRoot, 0);

    k_zero_cnt<<<NB, 256, 0, s1>>>();
    cudaEventRecord(evZ, s1);
    cudaStreamWaitEvent(s2, evZ, 0);
    // histogram halves in parallel
    k_hist<<<EBH, 256, 0, s1>>>(ei, 0, EH);
    k_hist<<<EBH, 256, 0, s2>>>(ei, EH, EE - EH);
    cudaEventRecord(evH, s2);
    cudaStreamWaitEvent(s1, evH, 0);
    // scan on s1
    k_scanA<<<SCAN_NT, 128, 0, s1>>>();
    k_scanC<<<SCAN_NT, 128, 0, s1>>>();
    cudaEventRecord(evS, s1);
    cudaStreamWaitEvent(s2, evS, 0);
    // fill halves in parallel
    k_fill<<<EBH, 256, 0, s1>>>(ei, 0, EH);
    k_fill<<<EBH, 256, 0, s2>>>(ei, EH, EE - EH);
    cudaEventRecord(evJ1, s1);
    cudaEventRecord(evJ2, s2);

    // prep + gemm0 on main (overlap the CSR chain)
    k_prep_w<<<(5 * 16384 + 255) / 256, 256>>>(conv_w, mlp_w);
    cudaLaunchKernelEx(&cfgGemm, k_gemm_mma,
                       x, nullH, (const u16*)whi, (const u16*)wlo, nullF, bufTh,
                       (int)NN, 0, 0, nullF, nullF, nullF, nullF, nullF, nullFo);

    cudaStreamWaitEvent(0, evJ1, 0);
    cudaStreamWaitEvent(0, evJ2, 0);  // join before gather0

    // layer 0
    cudaLaunchKernelEx(&cfgGather, k_gather,
                       (const __half*)bufTh, conv_b, bufH, stats, 0);

    // layer 1
    cudaLaunchKernelEx(&cfgGemm, k_gemm_mma,
                       nullF, (const __half*)bufH, (const u16*)(whi + 16384), (const u16*)(wlo + 16384),
                       nullF, bufTh, (int)NN, 0, 1, bn_g, bn_b, (const float*)stats,
                       nullF, nullF, nullFo);
    cudaLaunchKernelEx(&cfgGather, k_gather,
                       (const __half*)bufTh, conv_b + 128, bufH, stats + 256, 0);

    // layer 2
    cudaLaunchKernelEx(&cfgGemm, k_gemm_mma,
                       nullF, (const __half*)bufH, (const u16*)(whi + 32768), (const u16*)(wlo + 32768),
                       nullF, bufTh, (int)NN, 0, 1, bn_g + 128, bn_b + 128, (const float*)(stats + 256),
                       nullF, nullF, nullFo);
    cudaLaunchKernelEx(&cfgGather, k_gather,
                       (const __half*)bufTh, conv_b + 256, bufH, stats + 512, 1);

    // mlp1: tmode 2 (bn1(relu(h2)) quirk), relu(+bias) -> fp16 bufTh
    cudaLaunchKernelEx(&cfgGemm, k_gemm_mma,
                       nullF, (const __half*)bufH, (const u16*)(whi + 49152), (const u16*)(wlo + 49152),
                       mlp_b, bufTh, (int)NN, 1, 2, bn_g + 128, bn_b + 128, (const float*)(stats + 512),
                       nullF, nullF, nullFo);
    // mlp2 + fused sigmoid head
    cudaLaunchKernelEx(&cfgGemm, k_gemm_mma,
                       nullF, (const __half*)bufTh, (const u16*)(whi + 65536), (const u16*)(wlo + 65536),
                       mlp_b + 128, (__half*)nullptr, (int)NN, 2, 0, nullF, nullF, nullF,
                       out_w, out_b, (float*)d_out);
}